// round 12
// baseline (speedup 1.0000x reference)
#include <cuda_runtime.h>
#include <cuda_bf16.h>
#include <cstdint>

// Problem constants (fixed by reference)
#define NN    50000
#define EE    800000
#define ETOT  850000   // EE + NN self loops
#define FIN   768
#define HH    128
#define CC    9
#define MMID  3
#define BN_EPS 1e-5f
#define NSLICE 64

// ---------------- scratch (static device globals; no allocation) -------------
__device__ float g_cur[NN * HH];
__device__ float g_h[NN * HH];
__device__ float g_h9[NN * CC];
__device__ float g_as[NN];
__device__ float g_ad[NN];
__device__ int   g_deg[NN];
__device__ int   g_off[NN + 1];
__device__ int   g_fill[NN];
__device__ int   g_csrc[ETOT];
__device__ float g_wt[ETOT];                // per-edge normalized softmax weight
__device__ float g_bnslice[NSLICE * 256];   // [slice][0..127 sum, 128..255 sumsq]
__device__ float g_scale[HH];
__device__ float g_shift[HH];
// B limbs, per-chunk contiguous: [K/32][128 rows][32 cols] bf16
__device__ __nv_bfloat16 g_bh0[FIN * HH];
__device__ __nv_bfloat16 g_bl0[FIN * HH];
__device__ __nv_bfloat16 g_bhm[MMID * HH * HH];
__device__ __nv_bfloat16 g_blm[MMID * HH * HH];

__device__ __forceinline__ float leaky02(float e) { return e >= 0.f ? e : 0.2f * e; }
__device__ __forceinline__ float leaky01(float e) { return e >= 0.f ? e : 0.1f * e; }

// ================= mma.sync bf16 3-pass GEMM, 512-thread CTA =================
#define STRIDE 80
#define OFF_AH 0
#define OFF_AL 10240
#define OFF_BH 20480
#define OFF_BL 30720
#define STAGE_B 40960
#define OFF_MISC (2 * STAGE_B)
#define SMEM_DYN (OFF_MISC + 3072)

__device__ __forceinline__ uint32_t smem_u32(const void* p) {
    uint32_t a;
    asm("{ .reg .u64 t; cvta.to.shared.u64 t, %1; cvt.u32.u64 %0, t; }" : "=r"(a) : "l"(p));
    return a;
}

__device__ __forceinline__ void cpasync16(uint32_t dst, const void* src) {
    asm volatile("cp.async.ca.shared.global [%0], [%1], 16;" :: "r"(dst), "l"(src) : "memory");
}
__device__ __forceinline__ void cpcommit() { asm volatile("cp.async.commit_group;" ::: "memory"); }
__device__ __forceinline__ void cpwait0() { asm volatile("cp.async.wait_group 0;" ::: "memory"); }

__device__ __forceinline__ void split4(float4 v, uint64_t& h64, uint64_t& l64) {
    __nv_bfloat16 h0 = __float2bfloat16_rn(v.x);
    __nv_bfloat16 h1 = __float2bfloat16_rn(v.y);
    __nv_bfloat16 h2 = __float2bfloat16_rn(v.z);
    __nv_bfloat16 h3 = __float2bfloat16_rn(v.w);
    float l0 = v.x - __bfloat162float(h0);
    float l1 = v.y - __bfloat162float(h1);
    float l2 = v.z - __bfloat162float(h2);
    float l3 = v.w - __bfloat162float(h3);
    __nv_bfloat16 L0 = __float2bfloat16_rn(l0);
    __nv_bfloat16 L1 = __float2bfloat16_rn(l1);
    __nv_bfloat16 L2 = __float2bfloat16_rn(l2);
    __nv_bfloat16 L3 = __float2bfloat16_rn(l3);
    uint32_t hlo = ((uint32_t)__bfloat16_as_ushort(h1) << 16) | __bfloat16_as_ushort(h0);
    uint32_t hhi = ((uint32_t)__bfloat16_as_ushort(h3) << 16) | __bfloat16_as_ushort(h2);
    uint32_t llo = ((uint32_t)__bfloat16_as_ushort(L1) << 16) | __bfloat16_as_ushort(L0);
    uint32_t lhi = ((uint32_t)__bfloat16_as_ushort(L3) << 16) | __bfloat16_as_ushort(L2);
    h64 = ((uint64_t)hhi << 32) | hlo;
    l64 = ((uint64_t)lhi << 32) | llo;
}

__device__ __forceinline__ void ldsm4(uint32_t* r, uint32_t addr) {
    asm volatile("ldmatrix.sync.aligned.m8n8.x4.shared.b16 {%0,%1,%2,%3}, [%4];"
                 : "=r"(r[0]), "=r"(r[1]), "=r"(r[2]), "=r"(r[3]) : "r"(addr));
}

__device__ __forceinline__ void mma16816(float* d, const uint32_t* a, uint32_t b0, uint32_t b1) {
    asm volatile(
        "mma.sync.aligned.m16n8k16.row.col.f32.bf16.bf16.f32 "
        "{%0,%1,%2,%3}, {%4,%5,%6,%7}, {%8,%9}, {%0,%1,%2,%3};"
        : "+f"(d[0]), "+f"(d[1]), "+f"(d[2]), "+f"(d[3])
        : "r"(a[0]), "r"(a[1]), "r"(a[2]), "r"(a[3]), "r"(b0), "r"(b1));
}

// bnmode=1: BN finalize computed in-CTA from g_bnslice (gamma/beta required);
// block 0 publishes g_scale/g_shift for the following agg's residual path.
__global__ __launch_bounds__(512, 1)
void k_gemm_mma(const float* __restrict__ A,
                const __nv_bfloat16* __restrict__ Bh, const __nv_bfloat16* __restrict__ Bl,
                float* __restrict__ H, const float* __restrict__ a_s,
                const float* __restrict__ a_d, int K, int bnmode,
                const float* __restrict__ gamma, const float* __restrict__ beta,
                int gemmBlocks, const int* __restrict__ srcp, const int* __restrict__ dstp) {
    int tid = threadIdx.x;
    if (blockIdx.x >= gemmBlocks) {   // piggy-backed scatter (layer-0 launch)
        int e = (blockIdx.x - gemmBlocks) * 512 + tid;
        if (e < EE) {
            int dn = dstp[e];
            int pos = atomicAdd(&g_fill[dn], 1);
            g_csrc[pos] = srcp[e];
        } else if (e < ETOT) {
            int i = e - EE;
            int pos = atomicAdd(&g_fill[i], 1);
            g_csrc[pos] = i;
        }
        return;
    }

    extern __shared__ char sm[];
    float* vAs = (float*)(sm + OFF_MISC + 0);
    float* vAd = (float*)(sm + OFF_MISC + 512);
    float* rAs = (float*)(sm + OFF_MISC + 1024);
    float* rAd = (float*)(sm + OFF_MISC + 1536);
    float* sSc = (float*)(sm + OFF_MISC + 2048);
    float* sSh = (float*)(sm + OFF_MISC + 2560);
    uint32_t sb = smem_u32(sm);
    int lane = tid & 31, wid = tid >> 5;
    int rowBase = blockIdx.x * 128;

    if (tid < 128) {
        vAs[tid] = a_s[tid];
        vAd[tid] = a_d[tid];
        rAs[tid] = 0.f;
        rAd[tid] = 0.f;
        if (bnmode) {
            double s = 0.0, ss = 0.0;
#pragma unroll 8
            for (int i = 0; i < NSLICE; i++) {
                s += (double)g_bnslice[i * 256 + tid];
                ss += (double)g_bnslice[i * 256 + HH + tid];
            }
            double mean = s / (double)NN;
            double var = ss / (double)NN - mean * mean;
            float sc = gamma[tid] * (float)(1.0 / sqrt(var + (double)BN_EPS));
            float sh = beta[tid] - (float)mean * sc;
            sSc[tid] = sc;
            sSh[tid] = sh;
            if (blockIdx.x == 0) {
                g_scale[tid] = sc;
                g_shift[tid] = sh;
            }
        }
    }

    int arow = tid >> 2;
    int q = tid & 3;
    int gr = rowBase + arow;
    bool aval = gr < NN;
    const float* Arow = A + (size_t)(aval ? gr : 0) * K;
    uint32_t stbase = (uint32_t)(arow * STRIDE + q * 16);
    const char* bhsrc = (const char*)Bh + (size_t)arow * 64 + q * 16;
    const char* blsrc = (const char*)Bl + (size_t)arow * 64 + q * 16;
    __syncthreads();

    int mw = wid & 7, nw = wid >> 3;
    uint32_t aRel = (uint32_t)((mw * 16 + (lane & 15)) * STRIDE + ((lane >> 4) & 1) * 16);
    uint32_t bRel = (uint32_t)((nw * 64 + (lane & 7) + ((lane >> 4) & 1) * 8) * STRIDE +
                               ((lane >> 3) & 1) * 16);

    float d[8][4];
#pragma unroll
    for (int j = 0; j < 8; j++)
#pragma unroll
        for (int qq = 0; qq < 4; qq++) d[j][qq] = 0.f;

    int nch = K / 32;
    float4 av0, av1;

    auto loadA = [&](int c) {
        int k0 = c * 32 + q * 8;
        av0 = aval ? *(const float4*)(Arow + k0) : make_float4(0.f, 0.f, 0.f, 0.f);
        av1 = aval ? *(const float4*)(Arow + k0 + 4) : make_float4(0.f, 0.f, 0.f, 0.f);
        if (bnmode) {
            int cix = k0 & 127;
            av0.x = leaky01(av0.x * sSc[cix + 0] + sSh[cix + 0]);
            av0.y = leaky01(av0.y * sSc[cix + 1] + sSh[cix + 1]);
            av0.z = leaky01(av0.z * sSc[cix + 2] + sSh[cix + 2]);
            av0.w = leaky01(av0.w * sSc[cix + 3] + sSh[cix + 3]);
            av1.x = leaky01(av1.x * sSc[cix + 4] + sSh[cix + 4]);
            av1.y = leaky01(av1.y * sSc[cix + 5] + sSh[cix + 5]);
            av1.z = leaky01(av1.z * sSc[cix + 6] + sSh[cix + 6]);
            av1.w = leaky01(av1.w * sSc[cix + 7] + sSh[cix + 7]);
        }
    };
    auto storeA = [&](int stage) {
        char* st = sm + stage * STAGE_B;
        uint64_t h0, l0, h1, l1;
        split4(av0, h0, l0);
        split4(av1, h1, l1);
        *(uint64_t*)(st + OFF_AH + stbase) = h0;
        *(uint64_t*)(st + OFF_AH + stbase + 8) = h1;
        *(uint64_t*)(st + OFF_AL + stbase) = l0;
        *(uint64_t*)(st + OFF_AL + stbase + 8) = l1;
    };
    auto issueB = [&](int c, int stage) {
        uint32_t dst = sb + stage * STAGE_B;
        cpasync16(dst + OFF_BH + stbase, bhsrc + (size_t)c * 8192);
        cpasync16(dst + OFF_BL + stbase, blsrc + (size_t)c * 8192);
        cpcommit();
    };

    issueB(0, 0);
    loadA(0);
    storeA(0);
    cpwait0();
    __syncthreads();

    for (int c = 0; c < nch; c++) {
        int nxt = (c + 1) & 1;
        if (c + 1 < nch) {
            issueB(c + 1, nxt);
            loadA(c + 1);
        }
        uint32_t stg = (uint32_t)((c & 1) * STAGE_B);
        uint32_t aAddr = sb + stg + aRel;
        uint32_t bAddr = sb + stg + bRel;
#pragma unroll
        for (int s = 0; s < 2; s++) {
            uint32_t ah[4], al[4];
            ldsm4(ah, aAddr + OFF_AH + s * 32);
            ldsm4(al, aAddr + OFF_AL + s * 32);
#pragma unroll
            for (int np = 0; np < 4; np++) {
                uint32_t bh[4], bl[4];
                ldsm4(bh, bAddr + OFF_BH + np * (16 * STRIDE) + s * 32);
                ldsm4(bl, bAddr + OFF_BL + np * (16 * STRIDE) + s * 32);
                mma16816(d[2 * np], ah, bh[0], bh[1]);
                mma16816(d[2 * np], ah, bl[0], bl[1]);
                mma16816(d[2 * np], al, bh[0], bh[1]);
                mma16816(d[2 * np + 1], ah, bh[2], bh[3]);
                mma16816(d[2 * np + 1], ah, bl[2], bl[3]);
                mma16816(d[2 * np + 1], al, bh[2], bh[3]);
            }
        }
        if (c + 1 < nch) storeA(nxt);
        cpwait0();
        __syncthreads();
    }

    int g = lane >> 2, t = lane & 3;
    {
        int r0 = mw * 16 + g;
        int r1 = r0 + 8;
        int gr0 = rowBase + r0, gr1 = rowBase + r1;
        float pas0 = 0.f, pad0 = 0.f, pas1 = 0.f, pad1 = 0.f;
#pragma unroll
        for (int nt = 0; nt < 8; nt++) {
            int c0 = nw * 64 + nt * 8 + t * 2;
            float d0 = d[nt][0], d1 = d[nt][1];
            float d2 = d[nt][2], d3 = d[nt][3];
            if (gr0 < NN) *(float2*)(H + (size_t)gr0 * HH + c0) = make_float2(d0, d1);
            if (gr1 < NN) *(float2*)(H + (size_t)gr1 * HH + c0) = make_float2(d2, d3);
            pas0 = fmaf(d0, vAs[c0], fmaf(d1, vAs[c0 + 1], pas0));
            pad0 = fmaf(d0, vAd[c0], fmaf(d1, vAd[c0 + 1], pad0));
            pas1 = fmaf(d2, vAs[c0], fmaf(d3, vAs[c0 + 1], pas1));
            pad1 = fmaf(d2, vAd[c0], fmaf(d3, vAd[c0 + 1], pad1));
        }
#pragma unroll
        for (int o = 1; o <= 2; o <<= 1) {
            pas0 += __shfl_xor_sync(0xffffffffu, pas0, o);
            pad0 += __shfl_xor_sync(0xffffffffu, pad0, o);
            pas1 += __shfl_xor_sync(0xffffffffu, pas1, o);
            pad1 += __shfl_xor_sync(0xffffffffu, pad1, o);
        }
        if (t == 0) {
            atomicAdd(&rAs[r0], pas0);
            atomicAdd(&rAd[r0], pad0);
            atomicAdd(&rAs[r1], pas1);
            atomicAdd(&rAd[r1], pad1);
        }
    }
    __syncthreads();
    if (tid < 128) {
        int grr = rowBase + tid;
        if (grr < NN) {
            g_as[grr] = rAs[tid];
            g_ad[grr] = rAd[tid];
        }
    }
}

// ---------------- prep: B limb precompute + edge degree count -----------------
#define LIMB_TOT (FIN * HH + MMID * HH * HH)
__global__ void k_prep(const float* __restrict__ W0, const float* __restrict__ Wm,
                       const int* __restrict__ dst) {
    int i = blockIdx.x * blockDim.x + threadIdx.x;
    if (i < FIN * HH) {
        int k = i >> 7, n = i & 127;
        float v = W0[i];
        __nv_bfloat16 h = __float2bfloat16_rn(v);
        __nv_bfloat16 l = __float2bfloat16_rn(v - __bfloat162float(h));
        int chunk = k >> 5, kk = k & 31;
        size_t o = ((size_t)chunk * 128 + n) * 32 + kk;
        g_bh0[o] = h;
        g_bl0[o] = l;
    } else if (i < LIMB_TOT) {
        int j = i - FIN * HH;
        int lidx = j / (HH * HH);
        int r = j % (HH * HH);
        int k = r >> 7, n = r & 127;
        float v = Wm[j];
        __nv_bfloat16 h = __float2bfloat16_rn(v);
        __nv_bfloat16 l = __float2bfloat16_rn(v - __bfloat162float(h));
        int chunk = k >> 5, kk = k & 31;
        size_t o = (size_t)lidx * HH * HH + ((size_t)chunk * 128 + n) * 32 + kk;
        g_bhm[o] = h;
        g_blm[o] = l;
    } else {
        int e = i - LIMB_TOT;
        if (e < EE) atomicAdd(&g_deg[dst[e]], 1);
    }
}

__global__ void k_offsets() {
    __shared__ int s[1024];
    const int CH = (NN + 1023) / 1024;
    int t = threadIdx.x;
    int base = t * CH;
    int sum = 0;
    for (int i = 0; i < CH; i++) {
        int r = base + i;
        if (r < NN) sum += g_deg[r] + 1;
    }
    s[t] = sum;
    __syncthreads();
    for (int dd = 1; dd < 1024; dd <<= 1) {
        int v = (t >= dd) ? s[t - dd] : 0;
        __syncthreads();
        s[t] += v;
        __syncthreads();
    }
    int run = (t == 0) ? 0 : s[t - 1];
    for (int i = 0; i < CH; i++) {
        int r = base + i;
        if (r < NN) {
            g_off[r] = run;
            g_fill[r] = run;
            run += g_deg[r] + 1;
        }
    }
    if (t == 0) g_off[NN] = ETOT;
}

// ---------------- GAT aggregation, H=128 (warp per dst node) -----------------
__global__ void k_agg128(const float* __restrict__ hf,
                         const float* __restrict__ cur,
                         const float* __restrict__ bias,
                         float* __restrict__ out, int epi) {
    __shared__ float sStage[8 * HH];
    __shared__ float sStageSq[8 * HH];
    int tid = threadIdx.x;
    int w = (blockIdx.x * blockDim.x + tid) >> 5;   // grid covers exactly NN warps
    int lane = tid & 31;
    int warp = tid >> 5;
    int beg = g_off[w], end = g_off[w + 1];
    float adn = g_ad[w];

    // ---- pass 1: online softmax ----
    float m = -1e30f, z = 0.f;
    for (int j = beg + lane; j < end; j += 32) {
        float e = leaky02(g_as[g_csrc[j]] + adn);
        float mn = fmaxf(m, e);
        z = z * __expf(m - mn) + __expf(e - mn);
        m = mn;
    }
#pragma unroll
    for (int o = 16; o; o >>= 1) {
        float mo = __shfl_xor_sync(0xffffffffu, m, o);
        float zo = __shfl_xor_sync(0xffffffffu, z, o);
        float mn = fmaxf(m, mo);
        z = z * __expf(m - mn) + zo * __expf(mo - mn);
        m = mn;
    }
    float inv = 1.f / z;

    // ---- pass 1b: write normalized weights ----
    for (int j = beg + lane; j < end; j += 32) {
        float e = leaky02(g_as[g_csrc[j]] + adn);
        g_wt[j] = __expf(e - m) * inv;
    }
    __syncwarp();

    // ---- pass 2: pure gather, x4 unrolled ----
    float4 acc = make_float4(0.f, 0.f, 0.f, 0.f);
    int j = beg;
    for (; j + 4 <= end; j += 4) {
        int s0 = g_csrc[j], s1 = g_csrc[j + 1], s2 = g_csrc[j + 2], s3 = g_csrc[j + 3];
        float w0 = g_wt[j], w1 = g_wt[j + 1], w2 = g_wt[j + 2], w3 = g_wt[j + 3];
        float4 h0 = *(const float4*)(hf + (size_t)s0 * HH + lane * 4);
        float4 h1 = *(const float4*)(hf + (size_t)s1 * HH + lane * 4);
        float4 h2 = *(const float4*)(hf + (size_t)s2 * HH + lane * 4);
        float4 h3 = *(const float4*)(hf + (size_t)s3 * HH + lane * 4);
        acc.x += w0 * h0.x + w1 * h1.x + w2 * h2.x + w3 * h3.x;
        acc.y += w0 * h0.y + w1 * h1.y + w2 * h2.y + w3 * h3.y;
        acc.z += w0 * h0.z + w1 * h1.z + w2 * h2.z + w3 * h3.z;
        acc.w += w0 * h0.w + w1 * h1.w + w2 * h2.w + w3 * h3.w;
    }
    for (; j < end; j++) {
        int s = g_csrc[j];
        float wg = g_wt[j];
        float4 hv = *(const float4*)(hf + (size_t)s * HH + lane * 4);
        acc.x += wg * hv.x;
        acc.y += wg * hv.y;
        acc.z += wg * hv.z;
        acc.w += wg * hv.w;
    }

    float4 bv = *(const float4*)(bias + lane * 4);
    float4 r;
    r.x = acc.x + bv.x;
    r.y = acc.y + bv.y;
    r.z = acc.z + bv.z;
    r.w = acc.w + bv.w;
    if (epi) {
        float4 cv = *(const float4*)(cur + (size_t)w * HH + lane * 4);
        float4 sc = *(const float4*)(g_scale + lane * 4);
        float4 sh = *(const float4*)(g_shift + lane * 4);
        r.x += leaky01(cv.x * sc.x + sh.x);
        r.y += leaky01(cv.y * sc.y + sh.y);
        r.z += leaky01(cv.z * sc.z + sh.z);
        r.w += leaky01(cv.w * sc.w + sh.w);
    }
    *(float4*)(out + (size_t)w * HH + lane * 4) = r;

    // ---- fused BN stats: stage per-warp, tree-reduce, one atomic/channel ----
    int c4 = lane * 4;
    *(float4*)&sStage[warp * HH + c4] = r;
    float4 r2 = make_float4(r.x * r.x, r.y * r.y, r.z * r.z, r.w * r.w);
    *(float4*)&sStageSq[warp * HH + c4] = r2;
    __syncthreads();
    int c = tid & 127;
    if (tid < 128) {
        float s = 0.f;
#pragma unroll
        for (int ww = 0; ww < 8; ww++) s += sStage[ww * HH + c];
        atomicAdd(&g_bnslice[(blockIdx.x & (NSLICE - 1)) * 256 + c], s);
    } else {
        float s = 0.f;
#pragma unroll
        for (int ww = 0; ww < 8; ww++) s += sStageSq[ww * HH + c];
        atomicAdd(&g_bnslice[(blockIdx.x & (NSLICE - 1)) * 256 + HH + c], s);
    }
}

// ---------------- BN finalize (final BN only; mid BNs folded into GEMM) -------
__global__ void k_bn_finalize(const float* __restrict__ gamma,
                              const float* __restrict__ beta) {
    int c = threadIdx.x;
    if (c >= HH) return;
    double s = 0.0, ss = 0.0;
    for (int i = 0; i < NSLICE; i++) {
        s += (double)g_bnslice[i * 256 + c];
        ss += (double)g_bnslice[i * 256 + HH + c];
    }
    double mean = s / (double)NN;
    double var = ss / (double)NN - mean * mean;
    float sc = gamma[c] * (float)(1.0 / sqrt(var + (double)BN_EPS));
    g_scale[c] = sc;
    g_shift[c] = beta[c] - (float)mean * sc;
}

// ---------------- final layer ------------------------------------------------
__global__ void k_gemm9(const float* __restrict__ cur, const float* __restrict__ W,
                        const float* __restrict__ a_s, const float* __restrict__ a_d) {
    __shared__ float sW[HH * CC];
    __shared__ float sS[CC], sD[CC];
    int tid = threadIdx.x;
    for (int i = tid; i < HH * CC; i += blockDim.x) sW[i] = W[i];
    if (tid < CC) { sS[tid] = a_s[tid]; sD[tid] = a_d[tid]; }
    __syncthreads();

    int w = (blockIdx.x * blockDim.x + tid) >> 5;
    int lane = tid & 31;
    if (w >= NN) return;
    const float* arow = cur + (size_t)w * HH;
    float a0 = leaky01(arow[lane] * g_scale[lane] + g_shift[lane]);
    float a1 = leaky01(arow[lane + 32] * g_scale[lane + 32] + g_shift[lane + 32]);
    float a2 = leaky01(arow[lane + 64] * g_scale[lane + 64] + g_shift[lane + 64]);
    float a3 = leaky01(arow[lane + 96] * g_scale[lane + 96] + g_shift[lane + 96]);
    float acc[CC];
#pragma unroll
    for (int c = 0; c < CC; c++) {
        acc[c] = a0 * sW[lane * CC + c] + a1 * sW[(lane + 32) * CC + c] +
                 a2 * sW[(lane + 64) * CC + c] + a3 * sW[(lane + 96) * CC + c];
    }
#pragma unroll
    for (int c = 0; c < CC; c++)
#pragma unroll
        for (int o = 16; o; o >>= 1) acc[c] += __shfl_xor_sync(0xffffffffu, acc[c], o);
    if (lane < CC) g_h9[(size_t)w * CC + lane] = acc[lane];
    if (lane == 0) {
        float ds = 0.f, dd = 0.f;
#pragma unroll
        for (int c = 0; c < CC; c++) {
            ds = fmaf(acc[c], sS[c], ds);
            dd = fmaf(acc[c], sD[c], dd);
        }
        g_as[w] = ds;
        g_ad[w] = dd;
    }
}

__global__ void k_agg9(const float* __restrict__ h9,
                       const float* __restrict__ bias,
                       float* __restrict__ out) {
    int tid = threadIdx.x;
    int w = (blockIdx.x * blockDim.x + tid) >> 5;
    int lane = tid & 31;
    if (w >= NN) return;
    int beg = g_off[w], end = g_off[w + 1];
    float adn = g_ad[w];

    float m = -1e30f, z = 0.f;
    for (int j = beg + lane; j < end; j += 32) {
        float e = leaky02(g_as[g_csrc[j]] + adn);
        float mn = fmaxf(m, e);
        z = z * __expf(m - mn) + __expf(e - mn);
        m = mn;
    }
#pragma unroll
    for (int o = 16; o; o >>= 1) {
        float mo = __shfl_xor_sync(0xffffffffu, m, o);
        float zo = __shfl_xor_sync(0xffffffffu, z, o);
        float mn = fmaxf(m, mo);
        z = z * __expf(m - mn) + zo * __expf(mo - mn);
        m = mn;
    }
    float inv = 1.f / z;

    for (int j = beg + lane; j < end; j += 32) {
        float e = leaky02(g_as[g_csrc[j]] + adn);
        g_wt[j] = __expf(e - m) * inv;
    }
    __syncwarp();

    float acc = 0.f;
    int j = beg;
    for (; j + 4 <= end; j += 4) {
        int s0 = g_csrc[j], s1 = g_csrc[j + 1], s2 = g_csrc[j + 2], s3 = g_csrc[j + 3];
        float w0 = g_wt[j], w1 = g_wt[j + 1], w2 = g_wt[j + 2], w3 = g_wt[j + 3];
        if (lane < CC) {
            acc += w0 * h9[(size_t)s0 * CC + lane] + w1 * h9[(size_t)s1 * CC + lane] +
                   w2 * h9[(size_t)s2 * CC + lane] + w3 * h9[(size_t)s3 * CC + lane];
        }
    }
    for (; j < end; j++) {
        int s = g_csrc[j];
        float wg = g_wt[j];
        if (lane < CC) acc += wg * h9[(size_t)s * CC + lane];
    }
    if (lane < CC) {
        float v = acc + bias[lane];
        out[(size_t)w * CC + lane] = leaky01(v);
    }
}

// ---------------- driver ------------------------------------------------------
extern "C" void kernel_launch(void* const* d_in, const int* in_sizes, int n_in,
                              void* d_out, int out_size) {
    const float* x    = (const float*)d_in[0];
    const int*   ei   = (const int*)d_in[1];
    const float* W0   = (const float*)d_in[4];
    const float* a0s  = (const float*)d_in[5];
    const float* a0d  = (const float*)d_in[6];
    const float* b0   = (const float*)d_in[7];
    const float* Wm   = (const float*)d_in[8];
    const float* ams  = (const float*)d_in[9];
    const float* amd  = (const float*)d_in[10];
    const float* bm   = (const float*)d_in[11];
    const float* W4   = (const float*)d_in[12];
    const float* a4s  = (const float*)d_in[13];
    const float* a4d  = (const float*)d_in[14];
    const float* b4   = (const float*)d_in[15];
    const float* gamma = (const float*)d_in[16];
    const float* beta  = (const float*)d_in[17];
    float* out = (float*)d_out;

    const int* srcp = ei;
    const int* dstp = ei + EE;

    float *p_cur, *p_h, *p_h9, *p_slice;
    __nv_bfloat16 *p_bh0, *p_bl0, *p_bhm, *p_blm;
    int* p_deg;
    cudaGetSymbolAddress((void**)&p_cur, g_cur);
    cudaGetSymbolAddress((void**)&p_h, g_h);
    cudaGetSymbolAddress((void**)&p_h9, g_h9);
    cudaGetSymbolAddress((void**)&p_slice, g_bnslice);
    cudaGetSymbolAddress((void**)&p_bh0, g_bh0);
    cudaGetSymbolAddress((void**)&p_bl0, g_bl0);
    cudaGetSymbolAddress((void**)&p_bhm, g_bhm);
    cudaGetSymbolAddress((void**)&p_blm, g_blm);
    cudaGetSymbolAddress((void**)&p_deg, g_deg);

    cudaFuncSetAttribute(k_gemm_mma, cudaFuncAttributeMaxDynamicSharedMemorySize, SMEM_DYN);

    int gemmBlocks = (NN + 127) / 128;
    int scatBlocks = (ETOT + 511) / 512;
    int wblocks = (NN + 7) / 8;          // 6250, exactly NN warps
    int prepBlocks = (LIMB_TOT + EE + 511) / 512;

    cudaMemsetAsync(p_deg, 0, NN * sizeof(int));                           // L1
    k_prep<<<prepBlocks, 512>>>(W0, Wm, dstp);                             // L2
    k_offsets<<<1, 1024>>>();                                              // L3
    cudaMemsetAsync(p_slice, 0, NSLICE * 256 * sizeof(float));             // L4
    cudaMemsetAsync(p_h9, 0, NN * CC * sizeof(float));                     // L5 (window align)
    k_gemm_mma<<<gemmBlocks + scatBlocks, 512, SMEM_DYN>>>(
        x, p_bh0, p_bl0, p_h, a0s, a0d, FIN, 0, nullptr, nullptr,
        gemmBlocks, srcp, dstp);                                           // L6 (profiled)
    k_agg128<<<wblocks, 256>>>(p_h, nullptr, b0, p_cur, 0);                // L7

    for (int i = 0; i < MMID; i++) {
        // GEMM reads g_bnslice (from prior agg) and finalizes BN in-CTA
        k_gemm_mma<<<gemmBlocks, 512, SMEM_DYN>>>(
            p_cur, p_bhm + (size_t)i * HH * HH, p_blm + (size_t)i * HH * HH,
            p_h, ams + i * HH, amd + i * HH, HH, 1, gamma + i * HH, beta + i * HH,
            gemmBlocks, nullptr, nullptr);
        cudaMemsetAsync(p_slice, 0, NSLICE * 256 * sizeof(float));
        k_agg128<<<wblocks, 256>>>(p_h, p_cur, bm + i * HH, p_cur, 1);
    }

    k_bn_finalize<<<1, HH>>>(gamma + MMID * HH, beta + MMID * HH);
    k_gemm9<<<wblocks, 256>>>(p_cur, W4, a4s, a4d);
    k_agg9<<<wblocks, 256>>>(p_h9, b4, out);
}

// round 13
// speedup vs baseline: 1.1651x; 1.1651x over previous
#include <cuda_runtime.h>
#include <cuda_bf16.h>
#include <cstdint>

// Problem constants (fixed by reference)
#define NN    50000
#define EE    800000
#define ETOT  850000   // EE + NN self loops
#define FIN   768
#define HH    128
#define CC    9
#define MMID  3
#define BN_EPS 1e-5f
#define NSLICE 64

// ---------------- scratch (static device globals; no allocation) -------------
__device__ float g_cur[NN * HH];
__device__ float g_h[NN * HH];
__device__ float g_h9[NN * CC];
__device__ float g_as[NN];
__device__ float g_ad[NN];
__device__ int   g_deg[NN];
__device__ int   g_off[NN + 1];
__device__ int   g_fill[NN];
__device__ int   g_csrc[ETOT];
__device__ float g_wt[ETOT];                // per-edge score, then normalized weight
__device__ float g_bnslice[NSLICE * 256];   // [slice][0..127 sum, 128..255 sumsq]
__device__ float g_scale[HH];
__device__ float g_shift[HH];
// B limbs, per-chunk contiguous: [K/32][128 rows][32 cols] bf16
__device__ __nv_bfloat16 g_bh0[FIN * HH];
__device__ __nv_bfloat16 g_bl0[FIN * HH];
__device__ __nv_bfloat16 g_bhm[MMID * HH * HH];
__device__ __nv_bfloat16 g_blm[MMID * HH * HH];

__device__ __forceinline__ float leaky02(float e) { return e >= 0.f ? e : 0.2f * e; }
__device__ __forceinline__ float leaky01(float e) { return e >= 0.f ? e : 0.1f * e; }

// ================= mma.sync bf16 3-pass GEMM, 512-thread CTA =================
#define STRIDE 80
#define OFF_AH 0
#define OFF_AL 10240
#define OFF_BH 20480
#define OFF_BL 30720
#define STAGE_B 40960
#define OFF_MISC (2 * STAGE_B)
#define SMEM_DYN (OFF_MISC + 3072)

__device__ __forceinline__ uint32_t smem_u32(const void* p) {
    uint32_t a;
    asm("{ .reg .u64 t; cvta.to.shared.u64 t, %1; cvt.u32.u64 %0, t; }" : "=r"(a) : "l"(p));
    return a;
}

__device__ __forceinline__ void cpasync16(uint32_t dst, const void* src) {
    asm volatile("cp.async.ca.shared.global [%0], [%1], 16;" :: "r"(dst), "l"(src) : "memory");
}
__device__ __forceinline__ void cpcommit() { asm volatile("cp.async.commit_group;" ::: "memory"); }
__device__ __forceinline__ void cpwait0() { asm volatile("cp.async.wait_group 0;" ::: "memory"); }

__device__ __forceinline__ void split4(float4 v, uint64_t& h64, uint64_t& l64) {
    __nv_bfloat16 h0 = __float2bfloat16_rn(v.x);
    __nv_bfloat16 h1 = __float2bfloat16_rn(v.y);
    __nv_bfloat16 h2 = __float2bfloat16_rn(v.z);
    __nv_bfloat16 h3 = __float2bfloat16_rn(v.w);
    float l0 = v.x - __bfloat162float(h0);
    float l1 = v.y - __bfloat162float(h1);
    float l2 = v.z - __bfloat162float(h2);
    float l3 = v.w - __bfloat162float(h3);
    __nv_bfloat16 L0 = __float2bfloat16_rn(l0);
    __nv_bfloat16 L1 = __float2bfloat16_rn(l1);
    __nv_bfloat16 L2 = __float2bfloat16_rn(l2);
    __nv_bfloat16 L3 = __float2bfloat16_rn(l3);
    uint32_t hlo = ((uint32_t)__bfloat16_as_ushort(h1) << 16) | __bfloat16_as_ushort(h0);
    uint32_t hhi = ((uint32_t)__bfloat16_as_ushort(h3) << 16) | __bfloat16_as_ushort(h2);
    uint32_t llo = ((uint32_t)__bfloat16_as_ushort(L1) << 16) | __bfloat16_as_ushort(L0);
    uint32_t lhi = ((uint32_t)__bfloat16_as_ushort(L3) << 16) | __bfloat16_as_ushort(L2);
    h64 = ((uint64_t)hhi << 32) | hlo;
    l64 = ((uint64_t)lhi << 32) | llo;
}

__device__ __forceinline__ void ldsm4(uint32_t* r, uint32_t addr) {
    asm volatile("ldmatrix.sync.aligned.m8n8.x4.shared.b16 {%0,%1,%2,%3}, [%4];"
                 : "=r"(r[0]), "=r"(r[1]), "=r"(r[2]), "=r"(r[3]) : "r"(addr));
}

__device__ __forceinline__ void mma16816(float* d, const uint32_t* a, uint32_t b0, uint32_t b1) {
    asm volatile(
        "mma.sync.aligned.m16n8k16.row.col.f32.bf16.bf16.f32 "
        "{%0,%1,%2,%3}, {%4,%5,%6,%7}, {%8,%9}, {%0,%1,%2,%3};"
        : "+f"(d[0]), "+f"(d[1]), "+f"(d[2]), "+f"(d[3])
        : "r"(a[0]), "r"(a[1]), "r"(a[2]), "r"(a[3]), "r"(b0), "r"(b1));
}

__global__ __launch_bounds__(512, 1)
void k_gemm_mma(const float* __restrict__ A,
                const __nv_bfloat16* __restrict__ Bh, const __nv_bfloat16* __restrict__ Bl,
                float* __restrict__ H, const float* __restrict__ a_s,
                const float* __restrict__ a_d, int K, int bnmode,
                int gemmBlocks, const int* __restrict__ srcp, const int* __restrict__ dstp) {
    int tid = threadIdx.x;
    if (blockIdx.x >= gemmBlocks) {   // piggy-backed scatter (layer-0 launch)
        int e = (blockIdx.x - gemmBlocks) * 512 + tid;
        if (e < EE) {
            int dn = dstp[e];
            int pos = atomicAdd(&g_fill[dn], 1);
            g_csrc[pos] = srcp[e];
        } else if (e < ETOT) {
            int i = e - EE;
            int pos = atomicAdd(&g_fill[i], 1);
            g_csrc[pos] = i;
        }
        return;
    }

    extern __shared__ char sm[];
    float* vAs = (float*)(sm + OFF_MISC + 0);
    float* vAd = (float*)(sm + OFF_MISC + 512);
    float* rAs = (float*)(sm + OFF_MISC + 1024);
    float* rAd = (float*)(sm + OFF_MISC + 1536);
    float* sSc = (float*)(sm + OFF_MISC + 2048);
    float* sSh = (float*)(sm + OFF_MISC + 2560);
    uint32_t sb = smem_u32(sm);
    int lane = tid & 31, wid = tid >> 5;
    int rowBase = blockIdx.x * 128;

    if (tid < 128) {
        vAs[tid] = a_s[tid];
        vAd[tid] = a_d[tid];
        rAs[tid] = 0.f;
        rAd[tid] = 0.f;
        if (bnmode) { sSc[tid] = g_scale[tid]; sSh[tid] = g_shift[tid]; }
    }

    int arow = tid >> 2;
    int q = tid & 3;
    int gr = rowBase + arow;
    bool aval = gr < NN;
    const float* Arow = A + (size_t)(aval ? gr : 0) * K;
    uint32_t stbase = (uint32_t)(arow * STRIDE + q * 16);
    const char* bhsrc = (const char*)Bh + (size_t)arow * 64 + q * 16;
    const char* blsrc = (const char*)Bl + (size_t)arow * 64 + q * 16;
    __syncthreads();

    int mw = wid & 7, nw = wid >> 3;
    uint32_t aRel = (uint32_t)((mw * 16 + (lane & 15)) * STRIDE + ((lane >> 4) & 1) * 16);
    uint32_t bRel = (uint32_t)((nw * 64 + (lane & 7) + ((lane >> 4) & 1) * 8) * STRIDE +
                               ((lane >> 3) & 1) * 16);

    float d[8][4];
#pragma unroll
    for (int j = 0; j < 8; j++)
#pragma unroll
        for (int qq = 0; qq < 4; qq++) d[j][qq] = 0.f;

    int nch = K / 32;
    float4 av0, av1;

    auto loadA = [&](int c) {
        int k0 = c * 32 + q * 8;
        av0 = aval ? *(const float4*)(Arow + k0) : make_float4(0.f, 0.f, 0.f, 0.f);
        av1 = aval ? *(const float4*)(Arow + k0 + 4) : make_float4(0.f, 0.f, 0.f, 0.f);
        if (bnmode) {
            int cix = k0 & 127;
            av0.x = leaky01(av0.x * sSc[cix + 0] + sSh[cix + 0]);
            av0.y = leaky01(av0.y * sSc[cix + 1] + sSh[cix + 1]);
            av0.z = leaky01(av0.z * sSc[cix + 2] + sSh[cix + 2]);
            av0.w = leaky01(av0.w * sSc[cix + 3] + sSh[cix + 3]);
            av1.x = leaky01(av1.x * sSc[cix + 4] + sSh[cix + 4]);
            av1.y = leaky01(av1.y * sSc[cix + 5] + sSh[cix + 5]);
            av1.z = leaky01(av1.z * sSc[cix + 6] + sSh[cix + 6]);
            av1.w = leaky01(av1.w * sSc[cix + 7] + sSh[cix + 7]);
        }
    };
    auto storeA = [&](int stage) {
        char* st = sm + stage * STAGE_B;
        uint64_t h0, l0, h1, l1;
        split4(av0, h0, l0);
        split4(av1, h1, l1);
        *(uint64_t*)(st + OFF_AH + stbase) = h0;
        *(uint64_t*)(st + OFF_AH + stbase + 8) = h1;
        *(uint64_t*)(st + OFF_AL + stbase) = l0;
        *(uint64_t*)(st + OFF_AL + stbase + 8) = l1;
    };
    auto issueB = [&](int c, int stage) {
        uint32_t dst = sb + stage * STAGE_B;
        cpasync16(dst + OFF_BH + stbase, bhsrc + (size_t)c * 8192);
        cpasync16(dst + OFF_BL + stbase, blsrc + (size_t)c * 8192);
        cpcommit();
    };

    issueB(0, 0);
    loadA(0);
    storeA(0);
    cpwait0();
    __syncthreads();

    for (int c = 0; c < nch; c++) {
        int nxt = (c + 1) & 1;
        if (c + 1 < nch) {
            issueB(c + 1, nxt);
            loadA(c + 1);
        }
        uint32_t stg = (uint32_t)((c & 1) * STAGE_B);
        uint32_t aAddr = sb + stg + aRel;
        uint32_t bAddr = sb + stg + bRel;
#pragma unroll
        for (int s = 0; s < 2; s++) {
            uint32_t ah[4], al[4];
            ldsm4(ah, aAddr + OFF_AH + s * 32);
            ldsm4(al, aAddr + OFF_AL + s * 32);
#pragma unroll
            for (int np = 0; np < 4; np++) {
                uint32_t bh[4], bl[4];
                ldsm4(bh, bAddr + OFF_BH + np * (16 * STRIDE) + s * 32);
                ldsm4(bl, bAddr + OFF_BL + np * (16 * STRIDE) + s * 32);
                mma16816(d[2 * np], ah, bh[0], bh[1]);
                mma16816(d[2 * np], ah, bl[0], bl[1]);
                mma16816(d[2 * np], al, bh[0], bh[1]);
                mma16816(d[2 * np + 1], ah, bh[2], bh[3]);
                mma16816(d[2 * np + 1], ah, bl[2], bl[3]);
                mma16816(d[2 * np + 1], al, bh[2], bh[3]);
            }
        }
        if (c + 1 < nch) storeA(nxt);
        cpwait0();
        __syncthreads();
    }

    int g = lane >> 2, t = lane & 3;
    {
        int r0 = mw * 16 + g;
        int r1 = r0 + 8;
        int gr0 = rowBase + r0, gr1 = rowBase + r1;
        float pas0 = 0.f, pad0 = 0.f, pas1 = 0.f, pad1 = 0.f;
#pragma unroll
        for (int nt = 0; nt < 8; nt++) {
            int c0 = nw * 64 + nt * 8 + t * 2;
            float d0 = d[nt][0], d1 = d[nt][1];
            float d2 = d[nt][2], d3 = d[nt][3];
            if (gr0 < NN) *(float2*)(H + (size_t)gr0 * HH + c0) = make_float2(d0, d1);
            if (gr1 < NN) *(float2*)(H + (size_t)gr1 * HH + c0) = make_float2(d2, d3);
            pas0 = fmaf(d0, vAs[c0], fmaf(d1, vAs[c0 + 1], pas0));
            pad0 = fmaf(d0, vAd[c0], fmaf(d1, vAd[c0 + 1], pad0));
            pas1 = fmaf(d2, vAs[c0], fmaf(d3, vAs[c0 + 1], pas1));
            pad1 = fmaf(d2, vAd[c0], fmaf(d3, vAd[c0 + 1], pad1));
        }
#pragma unroll
        for (int o = 1; o <= 2; o <<= 1) {
            pas0 += __shfl_xor_sync(0xffffffffu, pas0, o);
            pad0 += __shfl_xor_sync(0xffffffffu, pad0, o);
            pas1 += __shfl_xor_sync(0xffffffffu, pas1, o);
            pad1 += __shfl_xor_sync(0xffffffffu, pad1, o);
        }
        if (t == 0) {
            atomicAdd(&rAs[r0], pas0);
            atomicAdd(&rAd[r0], pad0);
            atomicAdd(&rAs[r1], pas1);
            atomicAdd(&rAd[r1], pad1);
        }
    }
    __syncthreads();
    if (tid < 128) {
        int grr = rowBase + tid;
        if (grr < NN) {
            g_as[grr] = rAs[tid];
            g_ad[grr] = rAd[tid];
        }
    }
}

// ---------------- prep: B limb precompute + edge degree count -----------------
#define LIMB_TOT (FIN * HH + MMID * HH * HH)
__global__ void k_prep(const float* __restrict__ W0, const float* __restrict__ Wm,
                       const int* __restrict__ dst) {
    int i = blockIdx.x * blockDim.x + threadIdx.x;
    if (i < FIN * HH) {
        int k = i >> 7, n = i & 127;
        float v = W0[i];
        __nv_bfloat16 h = __float2bfloat16_rn(v);
        __nv_bfloat16 l = __float2bfloat16_rn(v - __bfloat162float(h));
        int chunk = k >> 5, kk = k & 31;
        size_t o = ((size_t)chunk * 128 + n) * 32 + kk;
        g_bh0[o] = h;
        g_bl0[o] = l;
    } else if (i < LIMB_TOT) {
        int j = i - FIN * HH;
        int lidx = j / (HH * HH);
        int r = j % (HH * HH);
        int k = r >> 7, n = r & 127;
        float v = Wm[j];
        __nv_bfloat16 h = __float2bfloat16_rn(v);
        __nv_bfloat16 l = __float2bfloat16_rn(v - __bfloat162float(h));
        int chunk = k >> 5, kk = k & 31;
        size_t o = (size_t)lidx * HH * HH + ((size_t)chunk * 128 + n) * 32 + kk;
        g_bhm[o] = h;
        g_blm[o] = l;
    } else {
        int e = i - LIMB_TOT;
        if (e < EE) atomicAdd(&g_deg[dst[e]], 1);
    }
}

__global__ void k_offsets() {
    __shared__ int s[1024];
    const int CH = (NN + 1023) / 1024;
    int t = threadIdx.x;
    int base = t * CH;
    int sum = 0;
    for (int i = 0; i < CH; i++) {
        int r = base + i;
        if (r < NN) sum += g_deg[r] + 1;
    }
    s[t] = sum;
    __syncthreads();
    for (int dd = 1; dd < 1024; dd <<= 1) {
        int v = (t >= dd) ? s[t - dd] : 0;
        __syncthreads();
        s[t] += v;
        __syncthreads();
    }
    int run = (t == 0) ? 0 : s[t - 1];
    for (int i = 0; i < CH; i++) {
        int r = base + i;
        if (r < NN) {
            g_off[r] = run;
            g_fill[r] = run;
            run += g_deg[r] + 1;
        }
    }
    if (t == 0) g_off[NN] = ETOT;
}

// ---------------- GAT aggregation, H=128 (warp per dst node) -----------------
// Pass 1 computes softmax stats AND stashes raw scores e into g_wt (coalesced);
// pass 1b normalizes g_wt in place (coalesced RMW, no gathers).
// Pass 2 is a pure (csrc, wt)-driven gather. BN stats fused atomic-free.
__global__ void k_agg128(const float* __restrict__ hf,
                         const float* __restrict__ cur,
                         const float* __restrict__ bias,
                         float* __restrict__ out, int epi) {
    __shared__ float sStage[8 * HH];
    __shared__ float sStageSq[8 * HH];
    int tid = threadIdx.x;
    int w = (blockIdx.x * blockDim.x + tid) >> 5;   // grid covers exactly NN warps
    int lane = tid & 31;
    int warp = tid >> 5;
    int beg = g_off[w], end = g_off[w + 1];
    float adn = g_ad[w];

    // ---- pass 1: online softmax + stash raw scores ----
    float m = -1e30f, z = 0.f;
    for (int j = beg + lane; j < end; j += 32) {
        float e = leaky02(g_as[g_csrc[j]] + adn);
        g_wt[j] = e;
        float mn = fmaxf(m, e);
        z = z * __expf(m - mn) + __expf(e - mn);
        m = mn;
    }
#pragma unroll
    for (int o = 16; o; o >>= 1) {
        float mo = __shfl_xor_sync(0xffffffffu, m, o);
        float zo = __shfl_xor_sync(0xffffffffu, z, o);
        float mn = fmaxf(m, mo);
        z = z * __expf(m - mn) + zo * __expf(mo - mn);
        m = mn;
    }
    float inv = 1.f / z;

    // ---- pass 1b: normalize weights in place (coalesced) ----
    for (int j = beg + lane; j < end; j += 32) {
        g_wt[j] = __expf(g_wt[j] - m) * inv;
    }
    __syncwarp();

    // ---- pass 2: pure gather, x4 unrolled ----
    float4 acc = make_float4(0.f, 0.f, 0.f, 0.f);
    int j = beg;
    for (; j + 4 <= end; j += 4) {
        int s0 = g_csrc[j], s1 = g_csrc[j + 1], s2 = g_csrc[j + 2], s3 = g_csrc[j + 3];
        float w0 = g_wt[j], w1 = g_wt[j + 1], w2 = g_wt[j + 2], w3 = g_wt[j + 3];
        float4 h0 = *(const float4*)(hf + (size_t)s0 * HH + lane * 4);
        float4 h1 = *(const float4*)(hf + (size_t)s1 * HH + lane * 4);
        float4 h2 = *(const float4*)(hf + (size_t)s2 * HH + lane * 4);
        float4 h3 = *(const float4*)(hf + (size_t)s3 * HH + lane * 4);
        acc.x += w0 * h0.x + w1 * h1.x + w2 * h2.x + w3 * h3.x;
        acc.y += w0 * h0.y + w1 * h1.y + w2 * h2.y + w3 * h3.y;
        acc.z += w0 * h0.z + w1 * h1.z + w2 * h2.z + w3 * h3.z;
        acc.w += w0 * h0.w + w1 * h1.w + w2 * h2.w + w3 * h3.w;
    }
    for (; j < end; j++) {
        int s = g_csrc[j];
        float wg = g_wt[j];
        float4 hv = *(const float4*)(hf + (size_t)s * HH + lane * 4);
        acc.x += wg * hv.x;
        acc.y += wg * hv.y;
        acc.z += wg * hv.z;
        acc.w += wg * hv.w;
    }

    float4 bv = *(const float4*)(bias + lane * 4);
    float4 r;
    r.x = acc.x + bv.x;
    r.y = acc.y + bv.y;
    r.z = acc.z + bv.z;
    r.w = acc.w + bv.w;
    if (epi) {
        float4 cv = *(const float4*)(cur + (size_t)w * HH + lane * 4);
        float4 sc = *(const float4*)(g_scale + lane * 4);
        float4 sh = *(const float4*)(g_shift + lane * 4);
        r.x += leaky01(cv.x * sc.x + sh.x);
        r.y += leaky01(cv.y * sc.y + sh.y);
        r.z += leaky01(cv.z * sc.z + sh.z);
        r.w += leaky01(cv.w * sc.w + sh.w);
    }
    *(float4*)(out + (size_t)w * HH + lane * 4) = r;

    // ---- fused BN stats: stage per-warp, tree-reduce, one atomic/channel ----
    int c4 = lane * 4;
    *(float4*)&sStage[warp * HH + c4] = r;
    float4 r2 = make_float4(r.x * r.x, r.y * r.y, r.z * r.z, r.w * r.w);
    *(float4*)&sStageSq[warp * HH + c4] = r2;
    __syncthreads();
    int c = tid & 127;
    if (tid < 128) {
        float s = 0.f;
#pragma unroll
        for (int ww = 0; ww < 8; ww++) s += sStage[ww * HH + c];
        atomicAdd(&g_bnslice[(blockIdx.x & (NSLICE - 1)) * 256 + c], s);
    } else {
        float s = 0.f;
#pragma unroll
        for (int ww = 0; ww < 8; ww++) s += sStageSq[ww * HH + c];
        atomicAdd(&g_bnslice[(blockIdx.x & (NSLICE - 1)) * 256 + HH + c], s);
    }
}

// ---------------- BN finalize (reduce slices in fp64) -------------------------
__global__ void k_bn_finalize(const float* __restrict__ gamma,
                              const float* __restrict__ beta) {
    int c = threadIdx.x;
    if (c >= HH) return;
    double s = 0.0, ss = 0.0;
    for (int i = 0; i < NSLICE; i++) {
        s += (double)g_bnslice[i * 256 + c];
        ss += (double)g_bnslice[i * 256 + HH + c];
    }
    double mean = s / (double)NN;
    double var = ss / (double)NN - mean * mean;
    float sc = gamma[c] * (float)(1.0 / sqrt(var + (double)BN_EPS));
    g_scale[c] = sc;
    g_shift[c] = beta[c] - (float)mean * sc;
}

// ---------------- final layer ------------------------------------------------
__global__ void k_gemm9(const float* __restrict__ cur, const float* __restrict__ W,
                        const float* __restrict__ a_s, const float* __restrict__ a_d) {
    __shared__ float sW[HH * CC];
    __shared__ float sS[CC], sD[CC];
    int tid = threadIdx.x;
    for (int i = tid; i < HH * CC; i += blockDim.x) sW[i] = W[i];
    if (tid < CC) { sS[tid] = a_s[tid]; sD[tid] = a_d[tid]; }
    __syncthreads();

    int w = (blockIdx.x * blockDim.x + tid) >> 5;
    int lane = tid & 31;
    if (w >= NN) return;
    const float* arow = cur + (size_t)w * HH;
    float a0 = leaky01(arow[lane] * g_scale[lane] + g_shift[lane]);
    float a1 = leaky01(arow[lane + 32] * g_scale[lane + 32] + g_shift[lane + 32]);
    float a2 = leaky01(arow[lane + 64] * g_scale[lane + 64] + g_shift[lane + 64]);
    float a3 = leaky01(arow[lane + 96] * g_scale[lane + 96] + g_shift[lane + 96]);
    float acc[CC];
#pragma unroll
    for (int c = 0; c < CC; c++) {
        acc[c] = a0 * sW[lane * CC + c] + a1 * sW[(lane + 32) * CC + c] +
                 a2 * sW[(lane + 64) * CC + c] + a3 * sW[(lane + 96) * CC + c];
    }
#pragma unroll
    for (int c = 0; c < CC; c++)
#pragma unroll
        for (int o = 16; o; o >>= 1) acc[c] += __shfl_xor_sync(0xffffffffu, acc[c], o);
    if (lane < CC) g_h9[(size_t)w * CC + lane] = acc[lane];
    if (lane == 0) {
        float ds = 0.f, dd = 0.f;
#pragma unroll
        for (int c = 0; c < CC; c++) {
            ds = fmaf(acc[c], sS[c], ds);
            dd = fmaf(acc[c], sD[c], dd);
        }
        g_as[w] = ds;
        g_ad[w] = dd;
    }
}

__global__ void k_agg9(const float* __restrict__ h9,
                       const float* __restrict__ bias,
                       float* __restrict__ out) {
    int tid = threadIdx.x;
    int w = (blockIdx.x * blockDim.x + tid) >> 5;
    int lane = tid & 31;
    if (w >= NN) return;
    int beg = g_off[w], end = g_off[w + 1];
    float adn = g_ad[w];

    float m = -1e30f, z = 0.f;
    for (int j = beg + lane; j < end; j += 32) {
        float e = leaky02(g_as[g_csrc[j]] + adn);
        g_wt[j] = e;
        float mn = fmaxf(m, e);
        z = z * __expf(m - mn) + __expf(e - mn);
        m = mn;
    }
#pragma unroll
    for (int o = 16; o; o >>= 1) {
        float mo = __shfl_xor_sync(0xffffffffu, m, o);
        float zo = __shfl_xor_sync(0xffffffffu, z, o);
        float mn = fmaxf(m, mo);
        z = z * __expf(m - mn) + zo * __expf(mo - mn);
        m = mn;
    }
    float inv = 1.f / z;

    for (int j = beg + lane; j < end; j += 32) {
        g_wt[j] = __expf(g_wt[j] - m) * inv;
    }
    __syncwarp();

    float acc = 0.f;
    int j = beg;
    for (; j + 4 <= end; j += 4) {
        int s0 = g_csrc[j], s1 = g_csrc[j + 1], s2 = g_csrc[j + 2], s3 = g_csrc[j + 3];
        float w0 = g_wt[j], w1 = g_wt[j + 1], w2 = g_wt[j + 2], w3 = g_wt[j + 3];
        if (lane < CC) {
            acc += w0 * h9[(size_t)s0 * CC + lane] + w1 * h9[(size_t)s1 * CC + lane] +
                   w2 * h9[(size_t)s2 * CC + lane] + w3 * h9[(size_t)s3 * CC + lane];
        }
    }
    for (; j < end; j++) {
        int s = g_csrc[j];
        float wg = g_wt[j];
        if (lane < CC) acc += wg * h9[(size_t)s * CC + lane];
    }
    if (lane < CC) {
        float v = acc + bias[lane];
        out[(size_t)w * CC + lane] = leaky01(v);
    }
}

// ---------------- driver ------------------------------------------------------
extern "C" void kernel_launch(void* const* d_in, const int* in_sizes, int n_in,
                              void* d_out, int out_size) {
    const float* x    = (const float*)d_in[0];
    const int*   ei   = (const int*)d_in[1];
    const float* W0   = (const float*)d_in[4];
    const float* a0s  = (const float*)d_in[5];
    const float* a0d  = (const float*)d_in[6];
    const float* b0   = (const float*)d_in[7];
    const float* Wm   = (const float*)d_in[8];
    const float* ams  = (const float*)d_in[9];
    const float* amd  = (const float*)d_in[10];
    const float* bm   = (const float*)d_in[11];
    const float* W4   = (const float*)d_in[12];
    const float* a4s  = (const float*)d_in[13];
    const float* a4d  = (const float*)d_in[14];
    const float* b4   = (const float*)d_in[15];
    const float* gamma = (const float*)d_in[16];
    const float* beta  = (const float*)d_in[17];
    float* out = (float*)d_out;

    const int* srcp = ei;
    const int* dstp = ei + EE;

    float *p_cur, *p_h, *p_h9, *p_slice;
    __nv_bfloat16 *p_bh0, *p_bl0, *p_bhm, *p_blm;
    int* p_deg;
    cudaGetSymbolAddress((void**)&p_cur, g_cur);
    cudaGetSymbolAddress((void**)&p_h, g_h);
    cudaGetSymbolAddress((void**)&p_h9, g_h9);
    cudaGetSymbolAddress((void**)&p_slice, g_bnslice);
    cudaGetSymbolAddress((void**)&p_bh0, g_bh0);
    cudaGetSymbolAddress((void**)&p_bl0, g_bl0);
    cudaGetSymbolAddress((void**)&p_bhm, g_bhm);
    cudaGetSymbolAddress((void**)&p_blm, g_blm);
    cudaGetSymbolAddress((void**)&p_deg, g_deg);

    cudaFuncSetAttribute(k_gemm_mma, cudaFuncAttributeMaxDynamicSharedMemorySize, SMEM_DYN);

    int gemmBlocks = (NN + 127) / 128;
    int scatBlocks = (ETOT + 511) / 512;
    int wblocks = (NN + 7) / 8;          // 6250, exactly NN warps
    int prepBlocks = (LIMB_TOT + EE + 511) / 512;

    cudaMemsetAsync(p_deg, 0, NN * sizeof(int));
    k_prep<<<prepBlocks, 512>>>(W0, Wm, dstp);
    k_offsets<<<1, 1024>>>();
    cudaMemsetAsync(p_slice, 0, NSLICE * 256 * sizeof(float));
    k_gemm_mma<<<gemmBlocks + scatBlocks, 512, SMEM_DYN>>>(
        x, p_bh0, p_bl0, p_h, a0s, a0d, FIN, 0, gemmBlocks, srcp, dstp);
    k_agg128<<<wblocks, 256>>>(p_h, nullptr, b0, p_cur, 0);

    for (int i = 0; i < MMID; i++) {
        k_bn_finalize<<<1, HH>>>(gamma + i * HH, beta + i * HH);
        cudaMemsetAsync(p_slice, 0, NSLICE * 256 * sizeof(float));
        k_gemm_mma<<<gemmBlocks, 512, SMEM_DYN>>>(
            p_cur, p_bhm + (size_t)i * HH * HH, p_blm + (size_t)i * HH * HH,
            p_h, ams + i * HH, amd + i * HH, HH, 1, gemmBlocks, nullptr, nullptr);
        k_agg128<<<wblocks, 256>>>(p_h, p_cur, bm + i * HH, p_cur, 1);
    }

    k_bn_finalize<<<1, HH>>>(gamma + MMID * HH, beta + MMID * HH);
    k_gemm9<<<wblocks, 256>>>(p_cur, W4, a4s, a4d);
    k_agg9<<<wblocks, 256>>>(p_h9, b4, out);
}